// round 3
// baseline (speedup 1.0000x reference)
#include <cuda_runtime.h>

#define EPS 1e-7f
#define BB 16
#define LL 1024
#define DD 256
#define PP 20

// packed fp32x2 FMA: d = a*b + d on both 32-bit halves (sm_10x FFMA2)
#define FMA2(acc, a, b) \
    asm("fma.rn.f32x2 %0, %1, %2, %0;" : "+l"(acc) : "l"(a), "l"(b))
#define PACK_DUP(d, s) \
    asm("mov.b64 %0, {%1, %1};" : "=l"(d) : "r"(__float_as_uint(s)))

static __device__ __forceinline__ float lo32(unsigned long long u) {
    return __uint_as_float((unsigned)u);
}
static __device__ __forceinline__ float hi32(unsigned long long u) {
    return __uint_as_float((unsigned)(u >> 32));
}

// ---------------- scratch (static __device__, no allocation) ----------------
__device__ float g_inv1[BB*LL];          // 1/n1
__device__ float g_inv2[BB*LL];          // 1/n2
__device__ float g_Mpart[4*BB*DD*DD];    // m-split partial Gram matrices
__device__ float g_vpart[4*BB*DD];       // m-split partial v
__device__ float g_M[BB*DD*DD];          // reduced Gram
__device__ float g_v[BB*DD];             // reduced v
__device__ float g_w[BB*LL*DD];          // weighted = x1 @ M

// ---------------- K0: per-row inverse norms (warp per row) ----------------
__global__ __launch_bounds__(256) void k_norms(const float* __restrict__ s1,
                                               const float* __restrict__ s2) {
    int gw   = (blockIdx.x * 256 + threadIdx.x) >> 5;
    int lane = threadIdx.x & 31;
    const float* src; float* dst; int r;
    if (gw < BB*LL) { src = s1; dst = g_inv1; r = gw; }
    else            { src = s2; dst = g_inv2; r = gw - BB*LL; }
    const float4* p = reinterpret_cast<const float4*>(src) + (size_t)r * (DD/4);
    float4 a = p[lane];
    float4 b = p[lane + 32];
    float ss = a.x*a.x + a.y*a.y + a.z*a.z + a.w*a.w
             + b.x*b.x + b.y*b.y + b.z*b.z + b.w*b.w;
#pragma unroll
    for (int o = 16; o; o >>= 1) ss += __shfl_xor_sync(0xffffffffu, ss, o);
    if (lane == 0) dst[r] = rsqrtf(fmaxf(ss, EPS));
}

// ---------------- K1: Gram M[b] = s2^T diag(1/n2) s2 (m-split x4) -----------
// grid (b=16, jt=4, ms=4); block 256. Tile 256i x 64j, 8x8 per thread,
// FFMA2 with i-pairing (a pairs contiguous from sRaw, b mov-duplicated).
__global__ __launch_bounds__(256) void k_gram(const float* __restrict__ s2) {
    __shared__ float sRaw[16][256];
    __shared__ float sScl[16][64];
    __shared__ float sInv[16];
    int b = blockIdx.x, jt = blockIdx.y, ms = blockIdx.z;
    int j0 = jt * 64;
    int m0 = ms * 256;
    int tid = threadIdx.x;
    int ig = tid >> 3;      // 0..31 -> i rows ig*8..+7
    int jg = tid & 7;       // 0..7  -> j cols j0+jg*8..+7
    unsigned long long acc2[4][8];   // (C[i0+2ip][j], C[i0+2ip+1][j])
#pragma unroll
    for (int ip = 0; ip < 4; ip++)
#pragma unroll
        for (int j = 0; j < 8; j++) acc2[ip][j] = 0ull;
    float vreg = 0.f;
    const float* base = s2 + (size_t)b * LL * DD;

    for (int c = 0; c < 16; c++) {              // 16 chunks of 16 m-rows
        int mb = m0 + c * 16;
        __syncthreads();
        const float4* src = reinterpret_cast<const float4*>(base + (size_t)mb * DD);
#pragma unroll
        for (int t = 0; t < 4; t++) {
            int f4 = tid + t * 256;
            int row = f4 >> 6, c4 = f4 & 63;
            reinterpret_cast<float4*>(&sRaw[row][0])[c4] = src[row * 64 + c4];
        }
        if (tid < 16) sInv[tid] = g_inv2[b * LL + mb + tid];
        __syncthreads();
#pragma unroll
        for (int t = 0; t < 4; t++) {
            int idx = tid + t * 256;
            int row = idx >> 6, col = idx & 63;
            sScl[row][col] = sRaw[row][j0 + col] * sInv[row];
        }
        __syncthreads();
        if (tid < 64) {
#pragma unroll
            for (int m = 0; m < 16; m++) vreg += sScl[m][tid];
        }
#pragma unroll 4
        for (int m = 0; m < 16; m++) {
            // a: 4 contiguous i-pairs (two 128-bit LDS)
            ulonglong2 Ap0 = *reinterpret_cast<const ulonglong2*>(&sRaw[m][ig * 8]);
            ulonglong2 Ap1 = *reinterpret_cast<const ulonglong2*>(&sRaw[m][ig * 8 + 4]);
            unsigned long long a2[4] = {Ap0.x, Ap0.y, Ap1.x, Ap1.y};
            // b: 8 scalars, duplicated into both halves
            float4 B0 = *reinterpret_cast<const float4*>(&sScl[m][jg * 8]);
            float4 B1 = *reinterpret_cast<const float4*>(&sScl[m][jg * 8 + 4]);
            float bs[8] = {B0.x, B0.y, B0.z, B0.w, B1.x, B1.y, B1.z, B1.w};
            unsigned long long b2[8];
#pragma unroll
            for (int j = 0; j < 8; j++) PACK_DUP(b2[j], bs[j]);
#pragma unroll
            for (int ip = 0; ip < 4; ip++)
#pragma unroll
                for (int j = 0; j < 8; j++) FMA2(acc2[ip][j], a2[ip], b2[j]);
        }
    }

    float* dst = g_Mpart + ((size_t)ms * BB + b) * DD * DD;
#pragma unroll
    for (int ip = 0; ip < 4; ip++) {
        int rlo = ig * 8 + 2 * ip;
        float l0v[8], h0v[8];
#pragma unroll
        for (int j = 0; j < 8; j++) { l0v[j] = lo32(acc2[ip][j]); h0v[j] = hi32(acc2[ip][j]); }
        *(float4*)&dst[rlo * DD + j0 + jg * 8]           = make_float4(l0v[0], l0v[1], l0v[2], l0v[3]);
        *(float4*)&dst[rlo * DD + j0 + jg * 8 + 4]       = make_float4(l0v[4], l0v[5], l0v[6], l0v[7]);
        *(float4*)&dst[(rlo + 1) * DD + j0 + jg * 8]     = make_float4(h0v[0], h0v[1], h0v[2], h0v[3]);
        *(float4*)&dst[(rlo + 1) * DD + j0 + jg * 8 + 4] = make_float4(h0v[4], h0v[5], h0v[6], h0v[7]);
    }
    if (tid < 64) g_vpart[((size_t)ms * BB + b) * DD + j0 + tid] = vreg;
}

// ---------------- K1b: reduce the 4 m-split partials ----------------
__global__ __launch_bounds__(256) void k_reduce() {
    int idx = blockIdx.x * 256 + threadIdx.x;
    const int MF4 = BB * DD * DD / 4;
    if (idx < MF4) {
        const float4* p = reinterpret_cast<const float4*>(g_Mpart);
        float4 a = p[idx], b = p[idx + MF4], c = p[idx + 2*MF4], d = p[idx + 3*MF4];
        float4 s = make_float4(a.x+b.x+c.x+d.x, a.y+b.y+c.y+d.y,
                               a.z+b.z+c.z+d.z, a.w+b.w+c.w+d.w);
        reinterpret_cast<float4*>(g_M)[idx] = s;
    } else {
        int r = idx - MF4;
        const int VN = BB * DD;
        if (r < VN)
            g_v[r] = g_vpart[r] + g_vpart[r+VN] + g_vpart[r+2*VN] + g_vpart[r+3*VN];
    }
}

// ---------------- K2: weighted = x1 @ M[b] ----------------
// grid (b=16, lt=16); block 256. Tile 64l x 256j, 8x8 per thread,
// FFMA2 with j-pairing (b pairs contiguous from sM, a mov-duplicated).
__global__ __launch_bounds__(256) void k_weighted(const float* __restrict__ s1) {
    __shared__ float sX[64][36];      // x1 tile [l][k], pad 36 keeps 16B align
    __shared__ float sM[32][256];     // M chunk [k][j]
    int b = blockIdx.x, lt = blockIdx.y;
    int l0 = lt * 64;
    int tid = threadIdx.x;
    int lg = tid >> 5;    // 0..7  -> l rows lg*8..+7 (warp-uniform)
    int jg = tid & 31;    // 0..31 -> j cols jg*8..+7
    unsigned long long acc2[8][4];    // (C[i][j0+2jp], C[i][j0+2jp+1])
#pragma unroll
    for (int i = 0; i < 8; i++)
#pragma unroll
        for (int jp = 0; jp < 4; jp++) acc2[i][jp] = 0ull;

    // hoist the two row-inv values this thread stages
    float inv_t0 = g_inv1[b * LL + l0 + (tid >> 3)];
    float inv_t1 = g_inv1[b * LL + l0 + ((tid + 256) >> 3)];

    for (int c = 0; c < 8; c++) {               // 8 chunks of 32 over d
        int k0 = c * 32;
        __syncthreads();
#pragma unroll
        for (int t = 0; t < 2; t++) {
            int f4 = tid + t * 256;
            int row = f4 >> 3, c4 = f4 & 7;
            float4 v = *reinterpret_cast<const float4*>(
                s1 + ((size_t)(b * LL + l0 + row)) * DD + k0 + c4 * 4);
            float inv = t ? inv_t1 : inv_t0;
            sX[row][c4*4+0] = v.x * inv;
            sX[row][c4*4+1] = v.y * inv;
            sX[row][c4*4+2] = v.z * inv;
            sX[row][c4*4+3] = v.w * inv;
        }
        const float4* msrc = reinterpret_cast<const float4*>(
            g_M + (size_t)b * DD * DD + (size_t)k0 * DD);
#pragma unroll
        for (int t = 0; t < 8; t++) {
            int f4 = tid + t * 256;
            reinterpret_cast<float4*>(&sM[0][0])[f4] = msrc[f4];
        }
        __syncthreads();
#pragma unroll 2
        for (int k = 0; k < 32; k++) {
            // b: 4 contiguous j-pairs
            ulonglong2 Bp0 = *reinterpret_cast<const ulonglong2*>(&sM[k][jg * 8]);
            ulonglong2 Bp1 = *reinterpret_cast<const ulonglong2*>(&sM[k][jg * 8 + 4]);
            unsigned long long b2[4] = {Bp0.x, Bp0.y, Bp1.x, Bp1.y};
            // a: 8 broadcast scalars, duplicated
            unsigned long long a2[8];
#pragma unroll
            for (int i = 0; i < 8; i++) PACK_DUP(a2[i], sX[lg * 8 + i][k]);
#pragma unroll
            for (int i = 0; i < 8; i++)
#pragma unroll
                for (int jp = 0; jp < 4; jp++) FMA2(acc2[i][jp], a2[i], b2[jp]);
        }
    }

    float* dst = g_w + ((size_t)(b * LL + l0)) * DD;
#pragma unroll
    for (int i = 0; i < 8; i++) {
        int row = lg * 8 + i;
        ulonglong2 s0; s0.x = acc2[i][0]; s0.y = acc2[i][1];
        ulonglong2 s1v; s1v.x = acc2[i][2]; s1v.y = acc2[i][3];
        *reinterpret_cast<ulonglong2*>(&dst[row * DD + jg * 8])     = s0;
        *reinterpret_cast<ulonglong2*>(&dst[row * DD + jg * 8 + 4]) = s1v;
    }
}

// ---------------- K3: epilogue — mav, perspective cosines (warp per row) ----
__global__ __launch_bounds__(256) void k_out(const float* __restrict__ s1,
                                             const float* __restrict__ ker,
                                             float* __restrict__ out) {
    __shared__ float ksq[PP * DD];
    __shared__ float vsh[DD];
    __shared__ float obuf[8][PP];
    int tid = threadIdx.x;
    int row0 = blockIdx.x * 8;
    int b = row0 >> 10;
    for (int i = tid; i < PP * DD; i += 256) { float t = ker[i]; ksq[i] = t * t; }
    vsh[tid] = g_v[b * DD + tid];
    __syncthreads();

    int w = tid >> 5, lane = tid & 31;
    int row = row0 + w;
    const float4* ap = reinterpret_cast<const float4*>(s1) + (size_t)row * 64;
    float4 A0 = ap[lane * 2], A1 = ap[lane * 2 + 1];
    const float4* wp = reinterpret_cast<const float4*>(g_w) + (size_t)row * 64;
    float4 W0 = wp[lane * 2], W1 = wp[lane * 2 + 1];
    float s[8]  = {A0.x, A0.y, A0.z, A0.w, A1.x, A1.y, A1.z, A1.w};
    float wv[8] = {W0.x, W0.y, W0.z, W0.w, W1.x, W1.y, W1.z, W1.w};

    float rs = 0.f;
    const float* vp = &vsh[lane * 8];
#pragma unroll
    for (int i = 0; i < 8; i++) rs += s[i] * vp[i];
#pragma unroll
    for (int o = 16; o; o >>= 1) rs += __shfl_xor_sync(0xffffffffu, rs, o);
    float denom = g_inv1[row] * rs + EPS;
    float invd = 1.0f / denom;

    float mv[8], sm[8], ssq[8], msq[8];
#pragma unroll
    for (int i = 0; i < 8; i++) {
        mv[i]  = wv[i] * invd;
        sm[i]  = s[i] * mv[i];
        ssq[i] = s[i] * s[i];
        msq[i] = mv[i] * mv[i];
    }

    for (int p = 0; p < PP; p++) {
        const float* kp = &ksq[p * DD + lane * 8];
        float4 K0 = *(const float4*)kp;
        float4 K1 = *(const float4*)(kp + 4);
        float kk[8] = {K0.x, K0.y, K0.z, K0.w, K1.x, K1.y, K1.z, K1.w};
        float n = 0.f, d1 = 0.f, d2 = 0.f;
#pragma unroll
        for (int i = 0; i < 8; i++) {
            n  += kk[i] * sm[i];
            d1 += kk[i] * ssq[i];
            d2 += kk[i] * msq[i];
        }
#pragma unroll
        for (int o = 16; o; o >>= 1) {
            n  += __shfl_xor_sync(0xffffffffu, n,  o);
            d1 += __shfl_xor_sync(0xffffffffu, d1, o);
            d2 += __shfl_xor_sync(0xffffffffu, d2, o);
        }
        if (lane == 0)
            obuf[w][p] = n * rsqrtf(fmaxf(d1, EPS)) * rsqrtf(fmaxf(d2, EPS));
    }
    __syncwarp();
    if (lane < PP) out[(size_t)row * PP + lane] = obuf[w][lane];
}

// ---------------- launch ----------------
extern "C" void kernel_launch(void* const* d_in, const int* in_sizes, int n_in,
                              void* d_out, int out_size) {
    const float* s1  = (const float*)d_in[0];   // [16,1024,256]
    const float* s2  = (const float*)d_in[1];   // [16,1024,256]
    const float* ker = (const float*)d_in[2];   // [20,256]
    float* out = (float*)d_out;                 // [16,1024,20]

    k_norms<<<4096, 256>>>(s1, s2);
    dim3 g1(16, 4, 4);
    k_gram<<<g1, 256>>>(s2);
    k_reduce<<<1040, 256>>>();
    dim3 g2(16, 16);
    k_weighted<<<g2, 256>>>(s1);
    k_out<<<2048, 256>>>(s1, ker, out);
}

// round 6
// speedup vs baseline: 1.3607x; 1.3607x over previous
#include <cuda_runtime.h>
#include <cuda_bf16.h>
#include <cstdint>

#define EPS 1e-7f
#define BB 16
#define LL 1024
#define DD 256
#define PP 20

#define SW128(o) ((o) ^ (((o) >> 3) & 0x70))

__device__ __forceinline__ uint32_t s2u(const void* p) {
    uint32_t a;
    asm("{ .reg .u64 t; cvta.to.shared.u64 t, %1; cvt.u32.u64 %0, t; }"
        : "=r"(a) : "l"(p));
    return a;
}

__device__ __forceinline__ void ldm_x4(uint32_t* r, uint32_t addr) {
    asm volatile("ldmatrix.sync.aligned.m8n8.x4.shared.b16 {%0,%1,%2,%3}, [%4];"
                 : "=r"(r[0]), "=r"(r[1]), "=r"(r[2]), "=r"(r[3]) : "r"(addr));
}

__device__ __forceinline__ void mma_bf16(float* c, const uint32_t* a, const uint32_t* b) {
    asm volatile(
        "mma.sync.aligned.m16n8k16.row.col.f32.bf16.bf16.f32 "
        "{%0,%1,%2,%3}, {%4,%5,%6,%7}, {%8,%9}, {%0,%1,%2,%3};"
        : "+f"(c[0]), "+f"(c[1]), "+f"(c[2]), "+f"(c[3])
        : "r"(a[0]), "r"(a[1]), "r"(a[2]), "r"(a[3]), "r"(b[0]), "r"(b[1]));
}

// ======================= scratch =======================
__device__ float g_inv1[BB*LL];
__device__ float g_inv2[BB*LL];
__device__ float g_vpart[4*BB*DD];
__device__ float g_v[BB*DD];
__device__ float g_w[BB*LL*DD];
__device__ __nv_bfloat16 g_s2tH[BB*DD*LL], g_s2tL[BB*DD*LL];   // [b][d][m]
__device__ __nv_bfloat16 g_y2tH[BB*DD*LL], g_y2tL[BB*DD*LL];   // [b][d][m]
__device__ __nv_bfloat16 g_x1h[BB*LL*DD],  g_x1l[BB*LL*DD];    // [b][l][d]
__device__ __nv_bfloat16 g_Mh[BB*DD*DD],   g_Ml[BB*DD*DD];     // [b][i][j] (symmetric)

// ======================= K0: inverse norms =======================
__global__ __launch_bounds__(256) void k_norms(const float* __restrict__ s1,
                                               const float* __restrict__ s2) {
    int gw   = (blockIdx.x * 256 + threadIdx.x) >> 5;
    int lane = threadIdx.x & 31;
    const float* src; float* dst; int r;
    if (gw < BB*LL) { src = s1; dst = g_inv1; r = gw; }
    else            { src = s2; dst = g_inv2; r = gw - BB*LL; }
    const float4* p = reinterpret_cast<const float4*>(src) + (size_t)r * (DD/4);
    float4 a = p[lane];
    float4 b = p[lane + 32];
    float ss = a.x*a.x + a.y*a.y + a.z*a.z + a.w*a.w
             + b.x*b.x + b.y*b.y + b.z*b.z + b.w*b.w;
#pragma unroll
    for (int o = 16; o; o >>= 1) ss += __shfl_xor_sync(0xffffffffu, ss, o);
    if (lane == 0) dst[r] = rsqrtf(fmaxf(ss, EPS));
}

// ======================= K1: x1 = s1*inv1, hi/lo bf16 =======================
__global__ __launch_bounds__(256) void k_split1(const float* __restrict__ s1) {
    int idx = blockIdx.x * 256 + threadIdx.x;     // float4 index
    int row = idx >> 6;
    float inv = g_inv1[row];
    float4 v = reinterpret_cast<const float4*>(s1)[idx];
    float x[4] = {v.x*inv, v.y*inv, v.z*inv, v.w*inv};
    __nv_bfloat16 h[4], l[4];
#pragma unroll
    for (int i = 0; i < 4; i++) {
        h[i] = __float2bfloat16(x[i]);
        l[i] = __float2bfloat16(x[i] - __bfloat162float(h[i]));
    }
    reinterpret_cast<__nv_bfloat162*>(g_x1h)[idx*2]   = {h[0], h[1]};
    reinterpret_cast<__nv_bfloat162*>(g_x1h)[idx*2+1] = {h[2], h[3]};
    reinterpret_cast<__nv_bfloat162*>(g_x1l)[idx*2]   = {l[0], l[1]};
    reinterpret_cast<__nv_bfloat162*>(g_x1l)[idx*2+1] = {l[2], l[3]};
}

// ======================= K2: transpose s2 -> s2t, y2t (hi/lo) ================
__global__ __launch_bounds__(256) void k_trans(const float* __restrict__ s2) {
    __shared__ float tile[32][33];
    __shared__ float sInv[32];
    int b = blockIdx.x, mt = blockIdx.y, dt = blockIdx.z;
    int tx = threadIdx.x & 31, ty = threadIdx.x >> 5;
    const float* src = s2 + ((size_t)(b * LL + mt * 32)) * DD + dt * 32;
#pragma unroll
    for (int r = 0; r < 4; r++)
        tile[ty + r*8][tx] = src[(ty + r*8) * DD + tx];
    if (threadIdx.x < 32) sInv[threadIdx.x] = g_inv2[b * LL + mt * 32 + threadIdx.x];
    __syncthreads();
#pragma unroll
    for (int r = 0; r < 4; r++) {
        int d = dt * 32 + ty + r*8;
        int m = mt * 32 + tx;
        float v = tile[tx][ty + r*8];
        float y = v * sInv[tx];
        size_t o = ((size_t)(b * DD + d)) * LL + m;
        __nv_bfloat16 vh = __float2bfloat16(v);
        g_s2tH[o] = vh;
        g_s2tL[o] = __float2bfloat16(v - __bfloat162float(vh));
        __nv_bfloat16 yh = __float2bfloat16(y);
        g_y2tH[o] = yh;
        g_y2tL[o] = __float2bfloat16(y - __bfloat162float(yh));
    }
}

// ======================= K3: v partial sums + reduce =======================
__global__ __launch_bounds__(256) void k_vpart(const float* __restrict__ s2) {
    __shared__ float sInv[256];
    int b = blockIdx.x, ms = blockIdx.y;
    int d = threadIdx.x;
    sInv[d] = g_inv2[b * LL + ms * 256 + d];
    __syncthreads();
    const float* base = s2 + ((size_t)b * LL + ms * 256) * DD;
    float acc = 0.f;
    for (int m0 = 0; m0 < 256; m0 += 8) {
#pragma unroll
        for (int mi = 0; mi < 8; mi++)
            acc += base[(m0 + mi) * DD + d] * sInv[m0 + mi];
    }
    g_vpart[((size_t)ms * BB + b) * DD + d] = acc;
}

__global__ __launch_bounds__(256) void k_vred() {
    int r = blockIdx.x * 256 + threadIdx.x;      // 0..4095
    const int VN = BB * DD;
    g_v[r] = g_vpart[r] + g_vpart[r+VN] + g_vpart[r+2*VN] + g_vpart[r+3*VN];
}

// ============ generic CTA tile: C[128 x 64] += A[128 x K] * B[64 x K]^T =====
// A,B K-major bf16 hi/lo; 3-pass split accumulation in fp32 via mma.sync.
// block 256 = 8 warps as 4(m) x 2(n); warp tile 32 x 32.
#define SM_AH 0
#define SM_AL 16384
#define SM_BH 32768
#define SM_BL 40960

__device__ __forceinline__ void gemm_core(
    int ktiles,
    const __nv_bfloat16* __restrict__ aH, const __nv_bfloat16* __restrict__ aL,
    const __nv_bfloat16* __restrict__ bH, const __nv_bfloat16* __restrict__ bL,
    int lda, int ldb, float acc[2][4][4], char* sm)
{
    uint32_t sb = s2u(sm);
    int tid = threadIdx.x;
    int lane = tid & 31, wid = tid >> 5;
    int m0 = (wid & 3) * 32;     // warp m origin in 128
    int n0 = (wid >> 2) * 32;    // warp n origin in 64

#pragma unroll
    for (int mi = 0; mi < 2; mi++)
#pragma unroll
        for (int ni = 0; ni < 4; ni++)
#pragma unroll
            for (int q = 0; q < 4; q++) acc[mi][ni][q] = 0.f;

    // precomputed ldmatrix smem offsets (within-tile, swizzled)
    uint32_t aoff[2], boff[2];
#pragma unroll
    for (int mi = 0; mi < 2; mi++) {
        int row = m0 + mi*16 + (lane & 15);
        aoff[mi] = SW128((uint32_t)(row * 128 + (lane >> 4) * 16));
    }
#pragma unroll
    for (int np = 0; np < 2; np++) {
        int row = n0 + np*16 + (lane & 7) + ((lane >> 4) << 3);
        boff[np] = SW128((uint32_t)(row * 128 + ((lane >> 3) & 1) * 16));
    }

    for (int kc = 0; kc < ktiles; kc++) {
        __syncthreads();
        // stage A: 128 rows x 64 k (hi+lo)
#pragma unroll
        for (int q = 0; q < 4; q++) {
            int idx = tid + q * 256;
            int row = idx >> 3, c = idx & 7;
            size_t go = (size_t)row * lda + (size_t)kc * 64 + c * 8;
            uint32_t so = SW128((uint32_t)(row * 128 + c * 16));
            *(uint4*)(sm + SM_AH + so) = *(const uint4*)(aH + go);
            *(uint4*)(sm + SM_AL + so) = *(const uint4*)(aL + go);
        }
        // stage B: 64 rows x 64 k (hi+lo)
#pragma unroll
        for (int q = 0; q < 2; q++) {
            int idx = tid + q * 256;
            int row = idx >> 3, c = idx & 7;
            size_t go = (size_t)row * ldb + (size_t)kc * 64 + c * 8;
            uint32_t so = SW128((uint32_t)(row * 128 + c * 16));
            *(uint4*)(sm + SM_BH + so) = *(const uint4*)(bH + go);
            *(uint4*)(sm + SM_BL + so) = *(const uint4*)(bL + go);
        }
        __syncthreads();

#pragma unroll
        for (int ks = 0; ks < 4; ks++) {
            uint32_t kb = ks * 32;    // 16 bf16 = 32 bytes; SW128 XOR-safe add
            uint32_t ah[2][4], al[2][4], bh[2][4], bl[2][4];
#pragma unroll
            for (int mi = 0; mi < 2; mi++) {
                ldm_x4(ah[mi], sb + SM_AH + (aoff[mi] ^ kb));
                ldm_x4(al[mi], sb + SM_AL + (aoff[mi] ^ kb));
            }
#pragma unroll
            for (int np = 0; np < 2; np++) {
                ldm_x4(bh[np], sb + SM_BH + (boff[np] ^ kb));
                ldm_x4(bl[np], sb + SM_BL + (boff[np] ^ kb));
            }
#pragma unroll
            for (int mi = 0; mi < 2; mi++)
#pragma unroll
                for (int ni = 0; ni < 4; ni++) {
                    const uint32_t* bph = &bh[ni >> 1][(ni & 1) * 2];
                    const uint32_t* bpl = &bl[ni >> 1][(ni & 1) * 2];
                    mma_bf16(acc[mi][ni], ah[mi], bph);
                    mma_bf16(acc[mi][ni], ah[mi], bpl);
                    mma_bf16(acc[mi][ni], al[mi], bph);
                }
        }
    }
}

// Gram: M[b][i][j] = sum_m s2t[b][i][m] * y2t[b][j][m]; K=1024.
__global__ __launch_bounds__(256) void k_gram_mma() {
    __shared__ __align__(128) char sm[49152];
    int b = blockIdx.x, it = blockIdx.y, jt = blockIdx.z;
    const __nv_bfloat16* aH = g_s2tH + ((size_t)(b * DD + it * 128)) * LL;
    const __nv_bfloat16* aL = g_s2tL + ((size_t)(b * DD + it * 128)) * LL;
    const __nv_bfloat16* bH = g_y2tH + ((size_t)(b * DD + jt * 64)) * LL;
    const __nv_bfloat16* bL = g_y2tL + ((size_t)(b * DD + jt * 64)) * LL;
    float acc[2][4][4];
    gemm_core(16, aH, aL, bH, bL, LL, LL, acc, sm);

    int lane = threadIdx.x & 31, wid = threadIdx.x >> 5;
    int m0 = (wid & 3) * 32, n0 = (wid >> 2) * 32;
#pragma unroll
    for (int mi = 0; mi < 2; mi++)
#pragma unroll
        for (int ni = 0; ni < 4; ni++) {
            int i = it * 128 + m0 + mi * 16 + (lane >> 2);
            int j = jt * 64 + n0 + ni * 8 + (lane & 3) * 2;
#pragma unroll
            for (int h = 0; h < 2; h++) {        // h=0: rows, h=1: rows+8
                float v0 = acc[mi][ni][h*2], v1 = acc[mi][ni][h*2+1];
                size_t o = ((size_t)(b * DD + i + h * 8)) * DD + j;
                __nv_bfloat16 h0 = __float2bfloat16(v0);
                __nv_bfloat16 h1 = __float2bfloat16(v1);
                *reinterpret_cast<__nv_bfloat162*>(&g_Mh[o]) = {h0, h1};
                *reinterpret_cast<__nv_bfloat162*>(&g_Ml[o]) = {
                    __float2bfloat16(v0 - __bfloat162float(h0)),
                    __float2bfloat16(v1 - __bfloat162float(h1))};
            }
        }
}

// weighted: W[b][l][j] = sum_k x1[b][l][k] * M[b][j][k]; K=256.
__global__ __launch_bounds__(256) void k_wt_mma() {
    __shared__ __align__(128) char sm[49152];
    int b = blockIdx.x, lt = blockIdx.y, jt = blockIdx.z;
    const __nv_bfloat16* aH = g_x1h + ((size_t)(b * LL + lt * 128)) * DD;
    const __nv_bfloat16* aL = g_x1l + ((size_t)(b * LL + lt * 128)) * DD;
    const __nv_bfloat16* bH = g_Mh + ((size_t)(b * DD + jt * 64)) * DD;
    const __nv_bfloat16* bL = g_Ml + ((size_t)(b * DD + jt * 64)) * DD;
    float acc[2][4][4];
    gemm_core(4, aH, aL, bH, bL, DD, DD, acc, sm);

    int lane = threadIdx.x & 31, wid = threadIdx.x >> 5;
    int m0 = (wid & 3) * 32, n0 = (wid >> 2) * 32;
#pragma unroll
    for (int mi = 0; mi < 2; mi++)
#pragma unroll
        for (int ni = 0; ni < 4; ni++) {
            int l = lt * 128 + m0 + mi * 16 + (lane >> 2);
            int j = jt * 64 + n0 + ni * 8 + (lane & 3) * 2;
#pragma unroll
            for (int h = 0; h < 2; h++) {
                size_t o = ((size_t)(b * LL + l + h * 8)) * DD + j;
                *reinterpret_cast<float2*>(&g_w[o]) =
                    make_float2(acc[mi][ni][h*2], acc[mi][ni][h*2+1]);
            }
        }
}

// ======================= K_out: epilogue =======================
__global__ __launch_bounds__(256) void k_out(const float* __restrict__ s1,
                                             const float* __restrict__ ker,
                                             float* __restrict__ out) {
    __shared__ float ksq[PP * DD];
    __shared__ float vsh[DD];
    __shared__ float obuf[8][PP];
    int tid = threadIdx.x;
    int row0 = blockIdx.x * 8;
    int b = row0 >> 10;
    for (int i = tid; i < PP * DD; i += 256) { float t = ker[i]; ksq[i] = t * t; }
    vsh[tid] = g_v[b * DD + tid];
    __syncthreads();

    int w = tid >> 5, lane = tid & 31;
    int row = row0 + w;
    const float4* ap = reinterpret_cast<const float4*>(s1) + (size_t)row * 64;
    float4 A0 = ap[lane * 2], A1 = ap[lane * 2 + 1];
    const float4* wp = reinterpret_cast<const float4*>(g_w) + (size_t)row * 64;
    float4 W0 = wp[lane * 2], W1 = wp[lane * 2 + 1];
    float s[8]  = {A0.x, A0.y, A0.z, A0.w, A1.x, A1.y, A1.z, A1.w};
    float wv[8] = {W0.x, W0.y, W0.z, W0.w, W1.x, W1.y, W1.z, W1.w};

    float rs = 0.f;
    const float* vp = &vsh[lane * 8];
#pragma unroll
    for (int i = 0; i < 8; i++) rs += s[i] * vp[i];
#pragma unroll
    for (int o = 16; o; o >>= 1) rs += __shfl_xor_sync(0xffffffffu, rs, o);
    float denom = g_inv1[row] * rs + EPS;
    float invd = 1.0f / denom;

    float mv[8], sm[8], ssq[8], msq[8];
#pragma unroll
    for (int i = 0; i < 8; i++) {
        mv[i]  = wv[i] * invd;
        sm[i]  = s[i] * mv[i];
        ssq[i] = s[i] * s[i];
        msq[i] = mv[i] * mv[i];
    }

    for (int p = 0; p < PP; p++) {
        const float* kp = &ksq[p * DD + lane * 8];
        float4 K0 = *(const float4*)kp;
        float4 K1 = *(const float4*)(kp + 4);
        float kk[8] = {K0.x, K0.y, K0.z, K0.w, K1.x, K1.y, K1.z, K1.w};
        float n = 0.f, d1 = 0.f, d2 = 0.f;
#pragma unroll
        for (int i = 0; i < 8; i++) {
            n  += kk[i] * sm[i];
            d1 += kk[i] * ssq[i];
            d2 += kk[i] * msq[i];
        }
#pragma unroll
        for (int o = 16; o; o >>= 1) {
            n  += __shfl_xor_sync(0xffffffffu, n,  o);
            d1 += __shfl_xor_sync(0xffffffffu, d1, o);
            d2 += __shfl_xor_sync(0xffffffffu, d2, o);
        }
        if (lane == 0)
            obuf[w][p] = n * rsqrtf(fmaxf(d1, EPS)) * rsqrtf(fmaxf(d2, EPS));
    }
    __syncwarp();
    if (lane < PP) out[(size_t)row * PP + lane] = obuf[w][lane];
}

// ======================= launch =======================
extern "C" void kernel_launch(void* const* d_in, const int* in_sizes, int n_in,
                              void* d_out, int out_size) {
    const float* s1  = (const float*)d_in[0];   // [16,1024,256]
    const float* s2  = (const float*)d_in[1];   // [16,1024,256]
    const float* ker = (const float*)d_in[2];   // [20,256]
    float* out = (float*)d_out;                 // [16,1024,20]

    k_norms<<<4096, 256>>>(s1, s2);
    k_split1<<<4096, 256>>>(s1);
    k_trans<<<dim3(16, 32, 8), 256>>>(s2);
    k_vpart<<<dim3(16, 4), 256>>>(s2);
    k_vred<<<16, 256>>>();
    k_gram_mma<<<dim3(16, 2, 4), 256>>>();
    k_wt_mma<<<dim3(16, 8, 4), 256>>>();
    k_out<<<2048, 256>>>(s1, ker, out);
}

// round 7
// speedup vs baseline: 1.5085x; 1.1086x over previous
#include <cuda_runtime.h>
#include <cuda_bf16.h>
#include <cstdint>

#define EPS 1e-7f
#define BB 16
#define LL 1024
#define DD 256
#define PP 20

#define SW128(o) ((o) ^ (((o) >> 3) & 0x70))

__device__ __forceinline__ uint32_t s2u(const void* p) {
    uint32_t a;
    asm("{ .reg .u64 t; cvta.to.shared.u64 t, %1; cvt.u32.u64 %0, t; }"
        : "=r"(a) : "l"(p));
    return a;
}

__device__ __forceinline__ void ldm_x4(uint32_t* r, uint32_t addr) {
    asm volatile("ldmatrix.sync.aligned.m8n8.x4.shared.b16 {%0,%1,%2,%3}, [%4];"
                 : "=r"(r[0]), "=r"(r[1]), "=r"(r[2]), "=r"(r[3]) : "r"(addr));
}

__device__ __forceinline__ void mma_bf16(float* c, const uint32_t* a, const uint32_t* b) {
    asm volatile(
        "mma.sync.aligned.m16n8k16.row.col.f32.bf16.bf16.f32 "
        "{%0,%1,%2,%3}, {%4,%5,%6,%7}, {%8,%9}, {%0,%1,%2,%3};"
        : "+f"(c[0]), "+f"(c[1]), "+f"(c[2]), "+f"(c[3])
        : "r"(a[0]), "r"(a[1]), "r"(a[2]), "r"(a[3]), "r"(b[0]), "r"(b[1]));
}

// ======================= scratch =======================
__device__ float g_inv1[BB*LL];
__device__ float g_inv2[BB*LL];
__device__ float g_vp[BB*32*DD];       // per-mt partial v sums
__device__ float g_v[BB*DD];
__device__ float g_w[BB*LL*DD];
__device__ __nv_bfloat16 g_zH[BB*DD*LL], g_zL[BB*DD*LL];       // z^T = (s2*sqrt(inv2))^T  [b][d][m]
__device__ __nv_bfloat16 g_x1h[BB*LL*DD], g_x1l[BB*LL*DD];     // [b][l][d]
__device__ __nv_bfloat16 g_Mh[BB*DD*DD],  g_Ml[BB*DD*DD];      // [b][i][j] (symmetric)

// ======== K0a: s1 fused — norm + hi/lo split, warp per row ========
__global__ __launch_bounds__(256) void k_prep1(const float* __restrict__ s1) {
    int row  = (blockIdx.x * 256 + threadIdx.x) >> 5;   // 0..16383
    int lane = threadIdx.x & 31;
    const float4* p = reinterpret_cast<const float4*>(s1) + (size_t)row * 64;
    float4 a = p[lane * 2], b = p[lane * 2 + 1];        // 8 contiguous floats
    float ss = a.x*a.x + a.y*a.y + a.z*a.z + a.w*a.w
             + b.x*b.x + b.y*b.y + b.z*b.z + b.w*b.w;
#pragma unroll
    for (int o = 16; o; o >>= 1) ss += __shfl_xor_sync(0xffffffffu, ss, o);
    float inv = rsqrtf(fmaxf(ss, EPS));
    if (lane == 0) g_inv1[row] = inv;
    float x[8] = {a.x*inv, a.y*inv, a.z*inv, a.w*inv,
                  b.x*inv, b.y*inv, b.z*inv, b.w*inv};
    __nv_bfloat16 h[8], l[8];
#pragma unroll
    for (int i = 0; i < 8; i++) {
        h[i] = __float2bfloat16(x[i]);
        l[i] = __float2bfloat16(x[i] - __bfloat162float(h[i]));
    }
    int o16 = row * 32 + lane;                          // uint4 index (8 bf16 = 16B)
    __nv_bfloat162 hh[4] = {{h[0],h[1]},{h[2],h[3]},{h[4],h[5]},{h[6],h[7]}};
    __nv_bfloat162 ll[4] = {{l[0],l[1]},{l[2],l[3]},{l[4],l[5]},{l[6],l[7]}};
    reinterpret_cast<uint4*>(g_x1h)[o16] = *reinterpret_cast<uint4*>(hh);
    reinterpret_cast<uint4*>(g_x1l)[o16] = *reinterpret_cast<uint4*>(ll);
}

// ======== K0b: s2 norms, warp per row ========
__global__ __launch_bounds__(256) void k_norms2(const float* __restrict__ s2) {
    int row  = (blockIdx.x * 256 + threadIdx.x) >> 5;
    int lane = threadIdx.x & 31;
    const float4* p = reinterpret_cast<const float4*>(s2) + (size_t)row * 64;
    float4 a = p[lane * 2], b = p[lane * 2 + 1];
    float ss = a.x*a.x + a.y*a.y + a.z*a.z + a.w*a.w
             + b.x*b.x + b.y*b.y + b.z*b.z + b.w*b.w;
#pragma unroll
    for (int o = 16; o; o >>= 1) ss += __shfl_xor_sync(0xffffffffu, ss, o);
    if (lane == 0) g_inv2[row] = rsqrtf(fmaxf(ss, EPS));
}

// ======== K1: transpose s2 -> z^T (hi/lo) + v partials ========
__global__ __launch_bounds__(256) void k_trans(const float* __restrict__ s2) {
    __shared__ float tile[32][33];
    __shared__ float sInvF[32];     // inv2
    __shared__ float sInvW[32];     // sqrt(inv2)
    int b = blockIdx.x, mt = blockIdx.y, dt = blockIdx.z;
    int tx = threadIdx.x & 31, ty = threadIdx.x >> 5;
    const float* src = s2 + ((size_t)(b * LL + mt * 32)) * DD + dt * 32;
#pragma unroll
    for (int r = 0; r < 4; r++)
        tile[ty + r*8][tx] = src[(ty + r*8) * DD + tx];
    if (threadIdx.x < 32) {
        float iv = g_inv2[b * LL + mt * 32 + threadIdx.x];
        sInvF[threadIdx.x] = iv;
        sInvW[threadIdx.x] = sqrtf(iv);
    }
    __syncthreads();
#pragma unroll
    for (int r = 0; r < 4; r++) {
        int d = dt * 32 + ty + r*8;
        int m = mt * 32 + tx;                  // tx == lane
        float v = tile[tx][ty + r*8];
        float z = v * sInvW[tx];
        size_t o = ((size_t)(b * DD + d)) * LL + m;
        __nv_bfloat16 zh = __float2bfloat16(z);
        g_zH[o] = zh;
        g_zL[o] = __float2bfloat16(z - __bfloat162float(zh));
        // v partial: sum over this block's 32 m for this d
        float pv = v * sInvF[tx];
#pragma unroll
        for (int of = 16; of; of >>= 1) pv += __shfl_xor_sync(0xffffffffu, pv, of);
        if (tx == 0) g_vp[((size_t)(b * 32 + mt)) * DD + d] = pv;
    }
}

// ======== K1b: reduce v partials over mt ========
__global__ __launch_bounds__(256) void k_vred() {
    int idx = blockIdx.x * 256 + threadIdx.x;   // 0..4095  (b*256+d)
    int b = idx >> 8, d = idx & 255;
    float acc = 0.f;
#pragma unroll
    for (int mt = 0; mt < 32; mt++)
        acc += g_vp[((size_t)(b * 32 + mt)) * DD + d];
    g_v[idx] = acc;
}

// ============ generic CTA tile: C[128 x 64] += A[128 x K] * B[64 x K]^T =====
#define SM_AH 0
#define SM_AL 16384
#define SM_BH 32768
#define SM_BL 40960

__device__ __forceinline__ void gemm_core(
    int ktiles,
    const __nv_bfloat16* __restrict__ aH, const __nv_bfloat16* __restrict__ aL,
    const __nv_bfloat16* __restrict__ bH, const __nv_bfloat16* __restrict__ bL,
    int lda, int ldb, float acc[2][4][4], char* sm)
{
    uint32_t sb = s2u(sm);
    int tid = threadIdx.x;
    int lane = tid & 31, wid = tid >> 5;
    int m0 = (wid & 3) * 32;
    int n0 = (wid >> 2) * 32;

#pragma unroll
    for (int mi = 0; mi < 2; mi++)
#pragma unroll
        for (int ni = 0; ni < 4; ni++)
#pragma unroll
            for (int q = 0; q < 4; q++) acc[mi][ni][q] = 0.f;

    uint32_t aoff[2], boff[2];
#pragma unroll
    for (int mi = 0; mi < 2; mi++) {
        int row = m0 + mi*16 + (lane & 15);
        aoff[mi] = SW128((uint32_t)(row * 128 + (lane >> 4) * 16));
    }
#pragma unroll
    for (int np = 0; np < 2; np++) {
        int row = n0 + np*16 + (lane & 7) + ((lane >> 4) << 3);
        boff[np] = SW128((uint32_t)(row * 128 + ((lane >> 3) & 1) * 16));
    }

    for (int kc = 0; kc < ktiles; kc++) {
        __syncthreads();
#pragma unroll
        for (int q = 0; q < 4; q++) {
            int idx = tid + q * 256;
            int row = idx >> 3, c = idx & 7;
            size_t go = (size_t)row * lda + (size_t)kc * 64 + c * 8;
            uint32_t so = SW128((uint32_t)(row * 128 + c * 16));
            *(uint4*)(sm + SM_AH + so) = *(const uint4*)(aH + go);
            *(uint4*)(sm + SM_AL + so) = *(const uint4*)(aL + go);
        }
#pragma unroll
        for (int q = 0; q < 2; q++) {
            int idx = tid + q * 256;
            int row = idx >> 3, c = idx & 7;
            size_t go = (size_t)row * ldb + (size_t)kc * 64 + c * 8;
            uint32_t so = SW128((uint32_t)(row * 128 + c * 16));
            *(uint4*)(sm + SM_BH + so) = *(const uint4*)(bH + go);
            *(uint4*)(sm + SM_BL + so) = *(const uint4*)(bL + go);
        }
        __syncthreads();

#pragma unroll
        for (int ks = 0; ks < 4; ks++) {
            uint32_t kb = ks * 32;
            uint32_t ah[2][4], al[2][4], bh[2][4], bl[2][4];
#pragma unroll
            for (int mi = 0; mi < 2; mi++) {
                ldm_x4(ah[mi], sb + SM_AH + (aoff[mi] ^ kb));
                ldm_x4(al[mi], sb + SM_AL + (aoff[mi] ^ kb));
            }
#pragma unroll
            for (int np = 0; np < 2; np++) {
                ldm_x4(bh[np], sb + SM_BH + (boff[np] ^ kb));
                ldm_x4(bl[np], sb + SM_BL + (boff[np] ^ kb));
            }
#pragma unroll
            for (int mi = 0; mi < 2; mi++)
#pragma unroll
                for (int ni = 0; ni < 4; ni++) {
                    const uint32_t* bph = &bh[ni >> 1][(ni & 1) * 2];
                    const uint32_t* bpl = &bl[ni >> 1][(ni & 1) * 2];
                    mma_bf16(acc[mi][ni], ah[mi], bph);
                    mma_bf16(acc[mi][ni], ah[mi], bpl);
                    mma_bf16(acc[mi][ni], al[mi], bph);
                }
        }
    }
}

// Gram: M[b][i][j] = sum_m z[m][i] * z[m][j]; K=1024.
__global__ __launch_bounds__(256) void k_gram_mma() {
    __shared__ __align__(128) char sm[49152];
    int b = blockIdx.x, it = blockIdx.y, jt = blockIdx.z;
    const __nv_bfloat16* aH = g_zH + ((size_t)(b * DD + it * 128)) * LL;
    const __nv_bfloat16* aL = g_zL + ((size_t)(b * DD + it * 128)) * LL;
    const __nv_bfloat16* bH = g_zH + ((size_t)(b * DD + jt * 64)) * LL;
    const __nv_bfloat16* bL = g_zL + ((size_t)(b * DD + jt * 64)) * LL;
    float acc[2][4][4];
    gemm_core(16, aH, aL, bH, bL, LL, LL, acc, sm);

    int lane = threadIdx.x & 31, wid = threadIdx.x >> 5;
    int m0 = (wid & 3) * 32, n0 = (wid >> 2) * 32;
#pragma unroll
    for (int mi = 0; mi < 2; mi++)
#pragma unroll
        for (int ni = 0; ni < 4; ni++) {
            int i = it * 128 + m0 + mi * 16 + (lane >> 2);
            int j = jt * 64 + n0 + ni * 8 + (lane & 3) * 2;
#pragma unroll
            for (int h = 0; h < 2; h++) {
                float v0 = acc[mi][ni][h*2], v1 = acc[mi][ni][h*2+1];
                size_t o = ((size_t)(b * DD + i + h * 8)) * DD + j;
                __nv_bfloat16 h0 = __float2bfloat16(v0);
                __nv_bfloat16 h1 = __float2bfloat16(v1);
                *reinterpret_cast<__nv_bfloat162*>(&g_Mh[o]) = {h0, h1};
                *reinterpret_cast<__nv_bfloat162*>(&g_Ml[o]) = {
                    __float2bfloat16(v0 - __bfloat162float(h0)),
                    __float2bfloat16(v1 - __bfloat162float(h1))};
            }
        }
}

// weighted: W[b][l][j] = sum_k x1[b][l][k] * M[b][j][k]; K=256.
__global__ __launch_bounds__(256) void k_wt_mma() {
    __shared__ __align__(128) char sm[49152];
    int b = blockIdx.x, lt = blockIdx.y, jt = blockIdx.z;
    const __nv_bfloat16* aH = g_x1h + ((size_t)(b * LL + lt * 128)) * DD;
    const __nv_bfloat16* aL = g_x1l + ((size_t)(b * LL + lt * 128)) * DD;
    const __nv_bfloat16* bH = g_Mh + ((size_t)(b * DD + jt * 64)) * DD;
    const __nv_bfloat16* bL = g_Ml + ((size_t)(b * DD + jt * 64)) * DD;
    float acc[2][4][4];
    gemm_core(4, aH, aL, bH, bL, DD, DD, acc, sm);

    int lane = threadIdx.x & 31, wid = threadIdx.x >> 5;
    int m0 = (wid & 3) * 32, n0 = (wid >> 2) * 32;
#pragma unroll
    for (int mi = 0; mi < 2; mi++)
#pragma unroll
        for (int ni = 0; ni < 4; ni++) {
            int l = lt * 128 + m0 + mi * 16 + (lane >> 2);
            int j = jt * 64 + n0 + ni * 8 + (lane & 3) * 2;
#pragma unroll
            for (int h = 0; h < 2; h++) {
                size_t o = ((size_t)(b * LL + l + h * 8)) * DD + j;
                *reinterpret_cast<float2*>(&g_w[o]) =
                    make_float2(acc[mi][ni][h*2], acc[mi][ni][h*2+1]);
            }
        }
}

// ======================= K_out: epilogue =======================
__global__ __launch_bounds__(256) void k_out(const float* __restrict__ s1,
                                             const float* __restrict__ ker,
                                             float* __restrict__ out) {
    __shared__ float ksq[PP * DD];
    __shared__ float vsh[DD];
    __shared__ float obuf[8][PP];
    int tid = threadIdx.x;
    int row0 = blockIdx.x * 8;
    int b = row0 >> 10;
    for (int i = tid; i < PP * DD; i += 256) { float t = ker[i]; ksq[i] = t * t; }
    vsh[tid] = g_v[b * DD + tid];
    __syncthreads();

    int w = tid >> 5, lane = tid & 31;
    int row = row0 + w;
    const float4* ap = reinterpret_cast<const float4*>(s1) + (size_t)row * 64;
    float4 A0 = ap[lane * 2], A1 = ap[lane * 2 + 1];
    const float4* wp = reinterpret_cast<const float4*>(g_w) + (size_t)row * 64;
    float4 W0 = wp[lane * 2], W1 = wp[lane * 2 + 1];
    float s[8]  = {A0.x, A0.y, A0.z, A0.w, A1.x, A1.y, A1.z, A1.w};
    float wv[8] = {W0.x, W0.y, W0.z, W0.w, W1.x, W1.y, W1.z, W1.w};

    float rs = 0.f;
    const float* vp = &vsh[lane * 8];
#pragma unroll
    for (int i = 0; i < 8; i++) rs += s[i] * vp[i];
#pragma unroll
    for (int o = 16; o; o >>= 1) rs += __shfl_xor_sync(0xffffffffu, rs, o);
    float denom = g_inv1[row] * rs + EPS;
    float invd = 1.0f / denom;

    float mv[8], sm[8], ssq[8], msq[8];
#pragma unroll
    for (int i = 0; i < 8; i++) {
        mv[i]  = wv[i] * invd;
        sm[i]  = s[i] * mv[i];
        ssq[i] = s[i] * s[i];
        msq[i] = mv[i] * mv[i];
    }

    for (int p = 0; p < PP; p++) {
        const float* kp = &ksq[p * DD + lane * 8];
        float4 K0 = *(const float4*)kp;
        float4 K1 = *(const float4*)(kp + 4);
        float kk[8] = {K0.x, K0.y, K0.z, K0.w, K1.x, K1.y, K1.z, K1.w};
        float n = 0.f, d1 = 0.f, d2 = 0.f;
#pragma unroll
        for (int i = 0; i < 8; i++) {
            n  += kk[i] * sm[i];
            d1 += kk[i] * ssq[i];
            d2 += kk[i] * msq[i];
        }
#pragma unroll
        for (int o = 16; o; o >>= 1) {
            n  += __shfl_xor_sync(0xffffffffu, n,  o);
            d1 += __shfl_xor_sync(0xffffffffu, d1, o);
            d2 += __shfl_xor_sync(0xffffffffu, d2, o);
        }
        if (lane == 0)
            obuf[w][p] = n * rsqrtf(fmaxf(d1, EPS)) * rsqrtf(fmaxf(d2, EPS));
    }
    __syncwarp();
    if (lane < PP) out[(size_t)row * PP + lane] = obuf[w][lane];
}

// ======================= launch =======================
extern "C" void kernel_launch(void* const* d_in, const int* in_sizes, int n_in,
                              void* d_out, int out_size) {
    const float* s1  = (const float*)d_in[0];   // [16,1024,256]
    const float* s2  = (const float*)d_in[1];   // [16,1024,256]
    const float* ker = (const float*)d_in[2];   // [20,256]
    float* out = (float*)d_out;                 // [16,1024,20]

    k_prep1<<<2048, 256>>>(s1);
    k_norms2<<<2048, 256>>>(s2);
    k_trans<<<dim3(16, 32, 8), 256>>>(s2);
    k_vred<<<16, 256>>>();
    k_gram_mma<<<dim3(16, 2, 4), 256>>>();
    k_wt_mma<<<dim3(16, 8, 4), 256>>>();
    k_out<<<2048, 256>>>(s1, ker, out);
}

// round 9
// speedup vs baseline: 1.6876x; 1.1187x over previous
#include <cuda_runtime.h>
#include <cuda_bf16.h>
#include <cstdint>

#define EPS 1e-7f
#define BB 16
#define LL 1024
#define DD 256
#define PP 20

#define SW128(o) ((o) ^ (((o) >> 3) & 0x70))

__device__ __forceinline__ uint32_t s2u(const void* p) {
    uint32_t a;
    asm("{ .reg .u64 t; cvta.to.shared.u64 t, %1; cvt.u32.u64 %0, t; }"
        : "=r"(a) : "l"(p));
    return a;
}

__device__ __forceinline__ void ldm_x4(uint32_t* r, uint32_t addr) {
    asm volatile("ldmatrix.sync.aligned.m8n8.x4.shared.b16 {%0,%1,%2,%3}, [%4];"
                 : "=r"(r[0]), "=r"(r[1]), "=r"(r[2]), "=r"(r[3]) : "r"(addr));
}

__device__ __forceinline__ void mma_bf16(float* c, const uint32_t* a, const uint32_t* b) {
    asm volatile(
        "mma.sync.aligned.m16n8k16.row.col.f32.bf16.bf16.f32 "
        "{%0,%1,%2,%3}, {%4,%5,%6,%7}, {%8,%9}, {%0,%1,%2,%3};"
        : "+f"(c[0]), "+f"(c[1]), "+f"(c[2]), "+f"(c[3])
        : "r"(a[0]), "r"(a[1]), "r"(a[2]), "r"(a[3]), "r"(b[0]), "r"(b[1]));
}

__device__ __forceinline__ void cp16(uint32_t dst, const void* src) {
    asm volatile("cp.async.cg.shared.global [%0], [%1], 16;" :: "r"(dst), "l"(src));
}
#define CP_COMMIT asm volatile("cp.async.commit_group;" ::: "memory")

// ======================= scratch =======================
__device__ float g_inv1[BB*LL];
__device__ float g_inv2[BB*LL];
__device__ float g_vp[BB*DD*32];       // v partials, [(b*DD+d)*32 + mt]
__device__ float g_v[BB*DD];
__device__ float g_w[BB*LL*DD];
__device__ __nv_bfloat16 g_zH[BB*DD*LL], g_zL[BB*DD*LL];       // z^T  [b][d][m]
__device__ __nv_bfloat16 g_x1h[BB*LL*DD], g_x1l[BB*LL*DD];     // [b][l][d]
__device__ __nv_bfloat16 g_Mh[BB*DD*DD],  g_Ml[BB*DD*DD];      // [b][i][j]

// ======== K0: fused norms (s1: + hi/lo split) — warp per row ========
__global__ __launch_bounds__(256) void k_prep(const float* __restrict__ s1,
                                              const float* __restrict__ s2) {
    int gw   = (blockIdx.x * 256 + threadIdx.x) >> 5;   // 0..32767
    int lane = threadIdx.x & 31;
    bool is1 = gw < BB*LL;
    int row = is1 ? gw : gw - BB*LL;
    const float* src = is1 ? s1 : s2;
    const float4* p = reinterpret_cast<const float4*>(src) + (size_t)row * 64;
    float4 a = p[lane * 2], b = p[lane * 2 + 1];
    float ss = a.x*a.x + a.y*a.y + a.z*a.z + a.w*a.w
             + b.x*b.x + b.y*b.y + b.z*b.z + b.w*b.w;
#pragma unroll
    for (int o = 16; o; o >>= 1) ss += __shfl_xor_sync(0xffffffffu, ss, o);
    float inv = rsqrtf(fmaxf(ss, EPS));
    if (!is1) {
        if (lane == 0) g_inv2[row] = inv;
        return;
    }
    if (lane == 0) g_inv1[row] = inv;
    float x[8] = {a.x*inv, a.y*inv, a.z*inv, a.w*inv,
                  b.x*inv, b.y*inv, b.z*inv, b.w*inv};
    __nv_bfloat16 h[8], l[8];
#pragma unroll
    for (int i = 0; i < 8; i++) {
        h[i] = __float2bfloat16(x[i]);
        l[i] = __float2bfloat16(x[i] - __bfloat162float(h[i]));
    }
    int o16 = row * 32 + lane;
    __nv_bfloat162 hh[4] = {{h[0],h[1]},{h[2],h[3]},{h[4],h[5]},{h[6],h[7]}};
    __nv_bfloat162 ll[4] = {{l[0],l[1]},{l[2],l[3]},{l[4],l[5]},{l[6],l[7]}};
    reinterpret_cast<uint4*>(g_x1h)[o16] = *reinterpret_cast<uint4*>(hh);
    reinterpret_cast<uint4*>(g_x1l)[o16] = *reinterpret_cast<uint4*>(ll);
}

// ======== K1: transpose s2 -> z^T (hi/lo) + v partials ========
__global__ __launch_bounds__(256) void k_trans(const float* __restrict__ s2) {
    __shared__ float tile[32][33];
    __shared__ float sInvF[32];
    __shared__ float sInvW[32];
    int b = blockIdx.x, mt = blockIdx.y, dt = blockIdx.z;
    int tx = threadIdx.x & 31, ty = threadIdx.x >> 5;
    const float* src = s2 + ((size_t)(b * LL + mt * 32)) * DD + dt * 32;
#pragma unroll
    for (int r = 0; r < 4; r++)
        tile[ty + r*8][tx] = src[(ty + r*8) * DD + tx];
    if (threadIdx.x < 32) {
        float iv = g_inv2[b * LL + mt * 32 + threadIdx.x];
        sInvF[threadIdx.x] = iv;
        sInvW[threadIdx.x] = sqrtf(iv);
    }
    __syncthreads();
#pragma unroll
    for (int r = 0; r < 4; r++) {
        int d = dt * 32 + ty + r*8;
        int m = mt * 32 + tx;
        float v = tile[tx][ty + r*8];
        float z = v * sInvW[tx];
        size_t o = ((size_t)(b * DD + d)) * LL + m;
        __nv_bfloat16 zh = __float2bfloat16(z);
        g_zH[o] = zh;
        g_zL[o] = __float2bfloat16(z - __bfloat162float(zh));
        float pv = v * sInvF[tx];
#pragma unroll
        for (int of = 16; of; of >>= 1) pv += __shfl_xor_sync(0xffffffffu, pv, of);
        if (tx == 0) g_vp[((size_t)(b * DD + d)) * 32 + mt] = pv;
    }
}

// ======== K1b: reduce v partials — warp per (b,d), coalesced ========
__global__ __launch_bounds__(256) void k_vred() {
    int gw   = (blockIdx.x * 256 + threadIdx.x) >> 5;   // 0..4095
    int lane = threadIdx.x & 31;
    float v = g_vp[(size_t)gw * 32 + lane];
#pragma unroll
    for (int o = 16; o; o >>= 1) v += __shfl_xor_sync(0xffffffffu, v, o);
    if (lane == 0) g_v[gw] = v;
}

// ============ pipelined CTA tile: C[128 x 64] += A[128 x K] * B[64 x K]^T ====
#define SM_AH 0
#define SM_AL 16384
#define SM_BH 32768
#define SM_BL 40960
#define BUFSZ 49152

__device__ __forceinline__ void stage_tile(
    uint32_t sb,
    const __nv_bfloat16* __restrict__ aH, const __nv_bfloat16* __restrict__ aL,
    const __nv_bfloat16* __restrict__ bH, const __nv_bfloat16* __restrict__ bL,
    int lda, int ldb, int kc, int tid)
{
#pragma unroll
    for (int q = 0; q < 4; q++) {
        int idx = tid + q * 256;
        int row = idx >> 3, c = idx & 7;
        size_t go = (size_t)row * lda + (size_t)kc * 64 + c * 8;
        uint32_t so = SW128((uint32_t)(row * 128 + c * 16));
        cp16(sb + SM_AH + so, aH + go);
        cp16(sb + SM_AL + so, aL + go);
    }
#pragma unroll
    for (int q = 0; q < 2; q++) {
        int idx = tid + q * 256;
        int row = idx >> 3, c = idx & 7;
        size_t go = (size_t)row * ldb + (size_t)kc * 64 + c * 8;
        uint32_t so = SW128((uint32_t)(row * 128 + c * 16));
        cp16(sb + SM_BH + so, bH + go);
        cp16(sb + SM_BL + so, bL + go);
    }
}

__device__ __forceinline__ void gemm_core(
    int ktiles,
    const __nv_bfloat16* __restrict__ aH, const __nv_bfloat16* __restrict__ aL,
    const __nv_bfloat16* __restrict__ bH, const __nv_bfloat16* __restrict__ bL,
    int lda, int ldb, float acc[2][4][4], char* sm)
{
    uint32_t sb = s2u(sm);
    int tid = threadIdx.x;
    int lane = tid & 31, wid = tid >> 5;
    int m0 = (wid & 3) * 32;
    int n0 = (wid >> 2) * 32;

#pragma unroll
    for (int mi = 0; mi < 2; mi++)
#pragma unroll
        for (int ni = 0; ni < 4; ni++)
#pragma unroll
            for (int q = 0; q < 4; q++) acc[mi][ni][q] = 0.f;

    uint32_t aoff[2], boff[2];
#pragma unroll
    for (int mi = 0; mi < 2; mi++) {
        int row = m0 + mi*16 + (lane & 15);
        aoff[mi] = SW128((uint32_t)(row * 128 + (lane >> 4) * 16));
    }
#pragma unroll
    for (int np = 0; np < 2; np++) {
        int row = n0 + np*16 + (lane & 7) + ((lane >> 4) << 3);
        boff[np] = SW128((uint32_t)(row * 128 + ((lane >> 3) & 1) * 16));
    }

    // prologue: stage chunk 0 into buffer 0
    stage_tile(sb, aH, aL, bH, bL, lda, ldb, 0, tid);
    CP_COMMIT;

    for (int kc = 0; kc < ktiles; kc++) {
        if (kc + 1 < ktiles) {
            stage_tile(sb + ((kc + 1) & 1) * BUFSZ, aH, aL, bH, bL, lda, ldb, kc + 1, tid);
            CP_COMMIT;
            asm volatile("cp.async.wait_group 1;" ::: "memory");
        } else {
            asm volatile("cp.async.wait_group 0;" ::: "memory");
        }
        __syncthreads();

        uint32_t sbuf = sb + (kc & 1) * BUFSZ;
#pragma unroll
        for (int ks = 0; ks < 4; ks++) {
            uint32_t kb = ks * 32;
            uint32_t ah[2][4], al[2][4], bh[2][4], bl[2][4];
#pragma unroll
            for (int mi = 0; mi < 2; mi++) {
                ldm_x4(ah[mi], sbuf + SM_AH + (aoff[mi] ^ kb));
                ldm_x4(al[mi], sbuf + SM_AL + (aoff[mi] ^ kb));
            }
#pragma unroll
            for (int np = 0; np < 2; np++) {
                ldm_x4(bh[np], sbuf + SM_BH + (boff[np] ^ kb));
                ldm_x4(bl[np], sbuf + SM_BL + (boff[np] ^ kb));
            }
#pragma unroll
            for (int mi = 0; mi < 2; mi++)
#pragma unroll
                for (int ni = 0; ni < 4; ni++) {
                    const uint32_t* bph = &bh[ni >> 1][(ni & 1) * 2];
                    const uint32_t* bpl = &bl[ni >> 1][(ni & 1) * 2];
                    mma_bf16(acc[mi][ni], ah[mi], bph);
                    mma_bf16(acc[mi][ni], ah[mi], bpl);
                    mma_bf16(acc[mi][ni], al[mi], bph);
                }
        }
        __syncthreads();   // compute done before this buffer is restaged
    }
}

// Gram: M[b][i][j] = sum_m z[m][i] * z[m][j]; K=1024.
__global__ __launch_bounds__(256) void k_gram_mma() {
    extern __shared__ __align__(128) char sm[];
    int b = blockIdx.x, it = blockIdx.y, jt = blockIdx.z;
    const __nv_bfloat16* aH = g_zH + ((size_t)(b * DD + it * 128)) * LL;
    const __nv_bfloat16* aL = g_zL + ((size_t)(b * DD + it * 128)) * LL;
    const __nv_bfloat16* bH = g_zH + ((size_t)(b * DD + jt * 64)) * LL;
    const __nv_bfloat16* bL = g_zL + ((size_t)(b * DD + jt * 64)) * LL;
    float acc[2][4][4];
    gemm_core(16, aH, aL, bH, bL, LL, LL, acc, sm);

    int lane = threadIdx.x & 31, wid = threadIdx.x >> 5;
    int m0 = (wid & 3) * 32, n0 = (wid >> 2) * 32;
#pragma unroll
    for (int mi = 0; mi < 2; mi++)
#pragma unroll
        for (int ni = 0; ni < 4; ni++) {
            int i = it * 128 + m0 + mi * 16 + (lane >> 2);
            int j = jt * 64 + n0 + ni * 8 + (lane & 3) * 2;
#pragma unroll
            for (int h = 0; h < 2; h++) {
                float v0 = acc[mi][ni][h*2], v1 = acc[mi][ni][h*2+1];
                size_t o = ((size_t)(b * DD + i + h * 8)) * DD + j;
                __nv_bfloat16 h0 = __float2bfloat16(v0);
                __nv_bfloat16 h1 = __float2bfloat16(v1);
                *reinterpret_cast<__nv_bfloat162*>(&g_Mh[o]) = {h0, h1};
                *reinterpret_cast<__nv_bfloat162*>(&g_Ml[o]) = {
                    __float2bfloat16(v0 - __bfloat162float(h0)),
                    __float2bfloat16(v1 - __bfloat162float(h1))};
            }
        }
}

// weighted: W[b][l][j] = sum_k x1[b][l][k] * M[b][j][k]; K=256.
__global__ __launch_bounds__(256) void k_wt_mma() {
    extern __shared__ __align__(128) char sm[];
    int b = blockIdx.x, lt = blockIdx.y, jt = blockIdx.z;
    const __nv_bfloat16* aH = g_x1h + ((size_t)(b * LL + lt * 128)) * DD;
    const __nv_bfloat16* aL = g_x1l + ((size_t)(b * LL + lt * 128)) * DD;
    const __nv_bfloat16* bH = g_Mh + ((size_t)(b * DD + jt * 64)) * DD;
    const __nv_bfloat16* bL = g_Ml + ((size_t)(b * DD + jt * 64)) * DD;
    float acc[2][4][4];
    gemm_core(4, aH, aL, bH, bL, DD, DD, acc, sm);

    int lane = threadIdx.x & 31, wid = threadIdx.x >> 5;
    int m0 = (wid & 3) * 32, n0 = (wid >> 2) * 32;
#pragma unroll
    for (int mi = 0; mi < 2; mi++)
#pragma unroll
        for (int ni = 0; ni < 4; ni++) {
            int l = lt * 128 + m0 + mi * 16 + (lane >> 2);
            int j = jt * 64 + n0 + ni * 8 + (lane & 3) * 2;
#pragma unroll
            for (int h = 0; h < 2; h++) {
                size_t o = ((size_t)(b * LL + l + h * 8)) * DD + j;
                *reinterpret_cast<float2*>(&g_w[o]) =
                    make_float2(acc[mi][ni][h*2], acc[mi][ni][h*2+1]);
            }
        }
}

// ======================= K_out: epilogue =======================
__global__ __launch_bounds__(256) void k_out(const float* __restrict__ s1,
                                             const float* __restrict__ ker,
                                             float* __restrict__ out) {
    __shared__ float ksq[PP * DD];
    __shared__ float vsh[DD];
    __shared__ float obuf[8][PP];
    int tid = threadIdx.x;
    int row0 = blockIdx.x * 8;
    int b = row0 >> 10;
    for (int i = tid; i < PP * DD; i += 256) { float t = ker[i]; ksq[i] = t * t; }
    vsh[tid] = g_v[b * DD + tid];
    __syncthreads();

    int w = tid >> 5, lane = tid & 31;
    int row = row0 + w;
    const float4* ap = reinterpret_cast<const float4*>(s1) + (size_t)row * 64;
    float4 A0 = ap[lane * 2], A1 = ap[lane * 2 + 1];
    const float4* wp = reinterpret_cast<const float4*>(g_w) + (size_t)row * 64;
    float4 W0 = wp[lane * 2], W1 = wp[lane * 2 + 1];
    float s[8]  = {A0.x, A0.y, A0.z, A0.w, A1.x, A1.y, A1.z, A1.w};
    float wv[8] = {W0.x, W0.y, W0.z, W0.w, W1.x, W1.y, W1.z, W1.w};

    float rs = 0.f;
    const float* vp = &vsh[lane * 8];
#pragma unroll
    for (int i = 0; i < 8; i++) rs += s[i] * vp[i];
#pragma unroll
    for (int o = 16; o; o >>= 1) rs += __shfl_xor_sync(0xffffffffu, rs, o);
    float denom = g_inv1[row] * rs + EPS;
    float invd = 1.0f / denom;

    float mv[8], sm[8], ssq[8], msq[8];
#pragma unroll
    for (int i = 0; i < 8; i++) {
        mv[i]  = wv[i] * invd;
        sm[i]  = s[i] * mv[i];
        ssq[i] = s[i] * s[i];
        msq[i] = mv[i] * mv[i];
    }

    for (int p = 0; p < PP; p++) {
        const float* kp = &ksq[p * DD + lane * 8];
        float4 K0 = *(const float4*)kp;
        float4 K1 = *(const float4*)(kp + 4);
        float kk[8] = {K0.x, K0.y, K0.z, K0.w, K1.x, K1.y, K1.z, K1.w};
        float n = 0.f, d1 = 0.f, d2 = 0.f;
#pragma unroll
        for (int i = 0; i < 8; i++) {
            n  += kk[i] * sm[i];
            d1 += kk[i] * ssq[i];
            d2 += kk[i] * msq[i];
        }
#pragma unroll
        for (int o = 16; o; o >>= 1) {
            n  += __shfl_xor_sync(0xffffffffu, n,  o);
            d1 += __shfl_xor_sync(0xffffffffu, d1, o);
            d2 += __shfl_xor_sync(0xffffffffu, d2, o);
        }
        if (lane == 0)
            obuf[w][p] = n * rsqrtf(fmaxf(d1, EPS)) * rsqrtf(fmaxf(d2, EPS));
    }
    __syncwarp();
    if (lane < PP) out[(size_t)row * PP + lane] = obuf[w][lane];
}

// ======================= launch =======================
extern "C" void kernel_launch(void* const* d_in, const int* in_sizes, int n_in,
                              void* d_out, int out_size) {
    const float* s1  = (const float*)d_in[0];   // [16,1024,256]
    const float* s2  = (const float*)d_in[1];   // [16,1024,256]
    const float* ker = (const float*)d_in[2];   // [20,256]
    float* out = (float*)d_out;                 // [16,1024,20]

    cudaFuncSetAttribute(k_gram_mma, cudaFuncAttributeMaxDynamicSharedMemorySize, 2*BUFSZ);
    cudaFuncSetAttribute(k_wt_mma,   cudaFuncAttributeMaxDynamicSharedMemorySize, 2*BUFSZ);

    k_prep<<<4096, 256>>>(s1, s2);
    k_trans<<<dim3(16, 32, 8), 256>>>(s2);
    k_vred<<<512, 256>>>();
    k_gram_mma<<<dim3(16, 2, 4), 256, 2*BUFSZ>>>();
    k_wt_mma<<<dim3(16, 8, 4), 256, 2*BUFSZ>>>();
    k_out<<<2048, 256>>>(s1, ker, out);
}

// round 11
// speedup vs baseline: 1.7043x; 1.0099x over previous
#include <cuda_runtime.h>
#include <cuda_bf16.h>
#include <cstdint>

#define EPS 1e-7f
#define BB 16
#define LL 1024
#define DD 256
#define PP 20

#define SW128(o) ((o) ^ (((o) >> 3) & 0x70))

__device__ __forceinline__ uint32_t s2u(const void* p) {
    uint32_t a;
    asm("{ .reg .u64 t; cvta.to.shared.u64 t, %1; cvt.u32.u64 %0, t; }"
        : "=r"(a) : "l"(p));
    return a;
}

__device__ __forceinline__ void ldm_x4(uint32_t* r, uint32_t addr) {
    asm volatile("ldmatrix.sync.aligned.m8n8.x4.shared.b16 {%0,%1,%2,%3}, [%4];"
                 : "=r"(r[0]), "=r"(r[1]), "=r"(r[2]), "=r"(r[3]) : "r"(addr));
}

__device__ __forceinline__ void mma_bf16(float* c, const uint32_t* a, const uint32_t* b) {
    asm volatile(
        "mma.sync.aligned.m16n8k16.row.col.f32.bf16.bf16.f32 "
        "{%0,%1,%2,%3}, {%4,%5,%6,%7}, {%8,%9}, {%0,%1,%2,%3};"
        : "+f"(c[0]), "+f"(c[1]), "+f"(c[2]), "+f"(c[3])
        : "r"(a[0]), "r"(a[1]), "r"(a[2]), "r"(a[3]), "r"(b[0]), "r"(b[1]));
}

__device__ __forceinline__ void cp16(uint32_t dst, const void* src) {
    asm volatile("cp.async.cg.shared.global [%0], [%1], 16;" :: "r"(dst), "l"(src));
}
#define CP_COMMIT asm volatile("cp.async.commit_group;" ::: "memory")

// ======================= scratch =======================
__device__ float g_vp[BB*DD*32];       // v partials, [(b*DD+d)*32 + mt]
__device__ float g_v[BB*DD];
__device__ float g_w[BB*LL*DD];
__device__ float g_Mp[2*BB*DD*DD];     // gram m-split fp32 partials
__device__ __nv_bfloat16 g_zH[BB*DD*LL], g_zL[BB*DD*LL];       // z^T  [b][d][m]
__device__ __nv_bfloat16 g_x1h[BB*LL*DD], g_x1l[BB*LL*DD];     // [b][l][d]
__device__ __nv_bfloat16 g_Mh[BB*DD*DD],  g_Ml[BB*DD*DD];      // [b][i][j]

// ======== K0: s1 — norm + hi/lo split, warp per row ========
__global__ __launch_bounds__(256) void k_prep(const float* __restrict__ s1) {
    int row  = (blockIdx.x * 256 + threadIdx.x) >> 5;   // 0..16383
    int lane = threadIdx.x & 31;
    const float4* p = reinterpret_cast<const float4*>(s1) + (size_t)row * 64;
    float4 a = p[lane * 2], b = p[lane * 2 + 1];
    float ss = a.x*a.x + a.y*a.y + a.z*a.z + a.w*a.w
             + b.x*b.x + b.y*b.y + b.z*b.z + b.w*b.w;
#pragma unroll
    for (int o = 16; o; o >>= 1) ss += __shfl_xor_sync(0xffffffffu, ss, o);
    float inv = rsqrtf(fmaxf(ss, EPS));
    float x[8] = {a.x*inv, a.y*inv, a.z*inv, a.w*inv,
                  b.x*inv, b.y*inv, b.z*inv, b.w*inv};
    __nv_bfloat16 h[8], l[8];
#pragma unroll
    for (int i = 0; i < 8; i++) {
        h[i] = __float2bfloat16(x[i]);
        l[i] = __float2bfloat16(x[i] - __bfloat162float(h[i]));
    }
    int o16 = row * 32 + lane;
    __nv_bfloat162 hh[4] = {{h[0],h[1]},{h[2],h[3]},{h[4],h[5]},{h[6],h[7]}};
    __nv_bfloat162 ll[4] = {{l[0],l[1]},{l[2],l[3]},{l[4],l[5]},{l[6],l[7]}};
    reinterpret_cast<uint4*>(g_x1h)[o16] = *reinterpret_cast<uint4*>(hh);
    reinterpret_cast<uint4*>(g_x1l)[o16] = *reinterpret_cast<uint4*>(ll);
}

// ======== K1: s2 fused — norms + transpose to z^T (hi/lo) + v partials ========
// block covers 32 m-rows x all 256 d; grid (b=16, mt=32)
__global__ __launch_bounds__(256) void k_trans(const float* __restrict__ s2) {
    __shared__ float tile[32][257];
    __shared__ float sInvF[32];
    __shared__ float sInvW[32];
    int b = blockIdx.x, mt = blockIdx.y;
    int tid = threadIdx.x, lane = tid & 31, w = tid >> 5;
    const float* src = s2 + ((size_t)(b * LL + mt * 32)) * DD;

    // phase 1: warp per row (4 rows per warp) — load, norm, stash raw
#pragma unroll
    for (int r = 0; r < 4; r++) {
        int row = w * 4 + r;
        const float4* p = reinterpret_cast<const float4*>(src + (size_t)row * DD);
        float4 a = p[lane * 2], bb = p[lane * 2 + 1];
        float* t = &tile[row][lane * 8];
        t[0]=a.x; t[1]=a.y; t[2]=a.z; t[3]=a.w;
        t[4]=bb.x; t[5]=bb.y; t[6]=bb.z; t[7]=bb.w;
        float ss = a.x*a.x + a.y*a.y + a.z*a.z + a.w*a.w
                 + bb.x*bb.x + bb.y*bb.y + bb.z*bb.z + bb.w*bb.w;
#pragma unroll
        for (int o = 16; o; o >>= 1) ss += __shfl_xor_sync(0xffffffffu, ss, o);
        if (lane == 0) {
            float inv = rsqrtf(fmaxf(ss, EPS));
            sInvF[row] = inv;
            sInvW[row] = sqrtf(inv);
        }
    }
    __syncthreads();

    // phase 2: v partial — thread per d
    {
        float acc = 0.f;
#pragma unroll 8
        for (int m = 0; m < 32; m++) acc += tile[m][tid] * sInvF[m];
        g_vp[((size_t)(b * DD + tid)) * 32 + mt] = acc;
    }

    // phase 3: transpose + scale + hi/lo split; thread -> (d, m-pair)
    int p2  = (tid & 15) * 2;    // m_local 2p, 2p+1
    int dof = tid >> 4;          // 0..15
#pragma unroll
    for (int it = 0; it < 16; it++) {
        int d = it * 16 + dof;
        float v0 = tile[p2][d],     v1 = tile[p2 + 1][d];
        float z0 = v0 * sInvW[p2],  z1 = v1 * sInvW[p2 + 1];
        __nv_bfloat16 h0 = __float2bfloat16(z0);
        __nv_bfloat16 h1 = __float2bfloat16(z1);
        __nv_bfloat16 l0 = __float2bfloat16(z0 - __bfloat162float(h0));
        __nv_bfloat16 l1 = __float2bfloat16(z1 - __bfloat162float(h1));
        size_t o = ((size_t)(b * DD + d)) * LL + mt * 32 + p2;
        *reinterpret_cast<__nv_bfloat162*>(g_zH + o) = {h0, h1};
        *reinterpret_cast<__nv_bfloat162*>(g_zL + o) = {l0, l1};
    }
}

// ======== K1b: reduce v partials — warp per (b,d), coalesced ========
__global__ __launch_bounds__(256) void k_vred() {
    int gw   = (blockIdx.x * 256 + threadIdx.x) >> 5;   // 0..4095
    int lane = threadIdx.x & 31;
    float v = g_vp[(size_t)gw * 32 + lane];
#pragma unroll
    for (int o = 16; o; o >>= 1) v += __shfl_xor_sync(0xffffffffu, v, o);
    if (lane == 0) g_v[gw] = v;
}

// ============ pipelined CTA tile: C[128 x 64] += A[128 x K] * B[64 x K]^T ====
#define SM_AH 0
#define SM_AL 16384
#define SM_BH 32768
#define SM_BL 40960
#define BUFSZ 49152

__device__ __forceinline__ void stage_tile(
    uint32_t sb,
    const __nv_bfloat16* __restrict__ aH, const __nv_bfloat16* __restrict__ aL,
    const __nv_bfloat16* __restrict__ bH, const __nv_bfloat16* __restrict__ bL,
    int lda, int ldb, int kc, int tid)
{
#pragma unroll
    for (int q = 0; q < 4; q++) {
        int idx = tid + q * 256;
        int row = idx >> 3, c = idx & 7;
        size_t go = (size_t)row * lda + (size_t)kc * 64 + c * 8;
        uint32_t so = SW128((uint32_t)(row * 128 + c * 16));
        cp16(sb + SM_AH + so, aH + go);
        cp16(sb + SM_AL + so, aL + go);
    }
#pragma unroll
    for (int q = 0; q < 2; q++) {
        int idx = tid + q * 256;
        int row = idx >> 3, c = idx & 7;
        size_t go = (size_t)row * ldb + (size_t)kc * 64 + c * 8;
        uint32_t so = SW128((uint32_t)(row * 128 + c * 16));
        cp16(sb + SM_BH + so, bH + go);
        cp16(sb + SM_BL + so, bL + go);
    }
}

__device__ __forceinline__ void gemm_core(
    int ktiles,
    const __nv_bfloat16* __restrict__ aH, const __nv_bfloat16* __restrict__ aL,
    const __nv_bfloat16* __restrict__ bH, const __nv_bfloat16* __restrict__ bL,
    int lda, int ldb, float acc[2][4][4], char* sm)
{
    uint32_t sb = s2u(sm);
    int tid = threadIdx.x;
    int lane = tid & 31, wid = tid >> 5;
    int m0 = (wid & 3) * 32;
    int n0 = (wid >> 2) * 32;

#pragma unroll
    for (int mi = 0; mi < 2; mi++)
#pragma unroll
        for (int ni = 0; ni < 4; ni++)
#pragma unroll
            for (int q = 0; q < 4; q++) acc[mi][ni][q] = 0.f;

    uint32_t aoff[2], boff[2];
#pragma unroll
    for (int mi = 0; mi < 2; mi++) {
        int row = m0 + mi*16 + (lane & 15);
        aoff[mi] = SW128((uint32_t)(row * 128 + (lane >> 4) * 16));
    }
#pragma unroll
    for (int np = 0; np < 2; np++) {
        int row = n0 + np*16 + (lane & 7) + ((lane >> 4) << 3);
        boff[np] = SW128((uint32_t)(row * 128 + ((lane >> 3) & 1) * 16));
    }

    stage_tile(sb, aH, aL, bH, bL, lda, ldb, 0, tid);
    CP_COMMIT;

    for (int kc = 0; kc < ktiles; kc++) {
        if (kc + 1 < ktiles) {
            stage_tile(sb + ((kc + 1) & 1) * BUFSZ, aH, aL, bH, bL, lda, ldb, kc + 1, tid);
            CP_COMMIT;
            asm volatile("cp.async.wait_group 1;" ::: "memory");
        } else {
            asm volatile("cp.async.wait_group 0;" ::: "memory");
        }
        __syncthreads();

        uint32_t sbuf = sb + (kc & 1) * BUFSZ;
#pragma unroll
        for (int ks = 0; ks < 4; ks++) {
            uint32_t kb = ks * 32;
            uint32_t ah[2][4], al[2][4], bh[2][4], bl[2][4];
#pragma unroll
            for (int mi = 0; mi < 2; mi++) {
                ldm_x4(ah[mi], sbuf + SM_AH + (aoff[mi] ^ kb));
                ldm_x4(al[mi], sbuf + SM_AL + (aoff[mi] ^ kb));
            }
#pragma unroll
            for (int np = 0; np < 2; np++) {
                ldm_x4(bh[np], sbuf + SM_BH + (boff[np] ^ kb));
                ldm_x4(bl[np], sbuf + SM_BL + (boff[np] ^ kb));
            }
#pragma unroll
            for (int mi = 0; mi < 2; mi++)
#pragma unroll
                for (int ni = 0; ni < 4; ni++) {
                    const uint32_t* bph = &bh[ni >> 1][(ni & 1) * 2];
                    const uint32_t* bpl = &bl[ni >> 1][(ni & 1) * 2];
                    mma_bf16(acc[mi][ni], ah[mi], bph);
                    mma_bf16(acc[mi][ni], ah[mi], bpl);
                    mma_bf16(acc[mi][ni], al[mi], bph);
                }
        }
        __syncthreads();
    }
}

// Gram partials: Mp[ms][b][i][j] = sum_{m in half ms} z[m][i]*z[m][j]; K=512.
__global__ __launch_bounds__(256) void k_gram_mma() {
    extern __shared__ __align__(128) char sm[];
    int b = blockIdx.x, it = blockIdx.y;
    int jt = blockIdx.z & 3, ms = blockIdx.z >> 2;
    const __nv_bfloat16* aH = g_zH + ((size_t)(b * DD + it * 128)) * LL + ms * 512;
    const __nv_bfloat16* aL = g_zL + ((size_t)(b * DD + it * 128)) * LL + ms * 512;
    const __nv_bfloat16* bH = g_zH + ((size_t)(b * DD + jt * 64)) * LL + ms * 512;
    const __nv_bfloat16* bL = g_zL + ((size_t)(b * DD + jt * 64)) * LL + ms * 512;
    float acc[2][4][4];
    gemm_core(8, aH, aL, bH, bL, LL, LL, acc, sm);

    int lane = threadIdx.x & 31, wid = threadIdx.x >> 5;
    int m0 = (wid & 3) * 32, n0 = (wid >> 2) * 32;
    float* dst = g_Mp + (size_t)ms * BB * DD * DD;
#pragma unroll
    for (int mi = 0; mi < 2; mi++)
#pragma unroll
        for (int ni = 0; ni < 4; ni++) {
            int i = it * 128 + m0 + mi * 16 + (lane >> 2);
            int j = jt * 64 + n0 + ni * 8 + (lane & 3) * 2;
#pragma unroll
            for (int h = 0; h < 2; h++) {
                size_t o = ((size_t)(b * DD + i + h * 8)) * DD + j;
                *reinterpret_cast<float2*>(&dst[o]) =
                    make_float2(acc[mi][ni][h*2], acc[mi][ni][h*2+1]);
            }
        }
}

// reduce the 2 gram partials and split to bf16 hi/lo
__global__ __launch_bounds__(256) void k_mred() {
    int idx = blockIdx.x * 256 + threadIdx.x;   // float4 index, 262144 total
    const int MF4 = BB * DD * DD / 4;
    const float4* p = reinterpret_cast<const float4*>(g_Mp);
    float4 a = p[idx], b = p[idx + MF4];
    float s[4] = {a.x+b.x, a.y+b.y, a.z+b.z, a.w+b.w};
    __nv_bfloat16 h[4], l[4];
#pragma unroll
    for (int i = 0; i < 4; i++) {
        h[i] = __float2bfloat16(s[i]);
        l[i] = __float2bfloat16(s[i] - __bfloat162float(h[i]));
    }
    reinterpret_cast<__nv_bfloat162*>(g_Mh)[idx*2]   = {h[0], h[1]};
    reinterpret_cast<__nv_bfloat162*>(g_Mh)[idx*2+1] = {h[2], h[3]};
    reinterpret_cast<__nv_bfloat162*>(g_Ml)[idx*2]   = {l[0], l[1]};
    reinterpret_cast<__nv_bfloat162*>(g_Ml)[idx*2+1] = {l[2], l[3]};
}

// weighted: W[b][l][j] = sum_k x1[b][l][k] * M[b][j][k]; K=256.
__global__ __launch_bounds__(256) void k_wt_mma() {
    extern __shared__ __align__(128) char sm[];
    int b = blockIdx.x, lt = blockIdx.y, jt = blockIdx.z;
    const __nv_bfloat16* aH = g_x1h + ((size_t)(b * LL + lt * 128)) * DD;
    const __nv_bfloat16* aL = g_x1l + ((size_t)(b * LL + lt * 128)) * DD;
    const __nv_bfloat16* bH = g_Mh + ((size_t)(b * DD + jt * 64)) * DD;
    const __nv_bfloat16* bL = g_Ml + ((size_t)(b * DD + jt * 64)) * DD;
    float acc[2][4][4];
    gemm_core(4, aH, aL, bH, bL, DD, DD, acc, sm);

    int lane = threadIdx.x & 31, wid = threadIdx.x >> 5;
    int m0 = (wid & 3) * 32, n0 = (wid >> 2) * 32;
#pragma unroll
    for (int mi = 0; mi < 2; mi++)
#pragma unroll
        for (int ni = 0; ni < 4; ni++) {
            int l = lt * 128 + m0 + mi * 16 + (lane >> 2);
            int j = jt * 64 + n0 + ni * 8 + (lane & 3) * 2;
#pragma unroll
            for (int h = 0; h < 2; h++) {
                size_t o = ((size_t)(b * LL + l + h * 8)) * DD + j;
                *reinterpret_cast<float2*>(&g_w[o]) =
                    make_float2(acc[mi][ni][h*2], acc[mi][ni][h*2+1]);
            }
        }
}

// ======================= K_out: epilogue (x1-based, scale-invariant) ========
__global__ __launch_bounds__(256) void k_out(const float* __restrict__ ker,
                                             float* __restrict__ out) {
    __shared__ float ksq[PP * DD];
    __shared__ float vsh[DD];
    __shared__ float obuf[8][PP];
    int tid = threadIdx.x;
    int row0 = blockIdx.x * 8;
    int b = row0 >> 10;
    for (int i = tid; i < PP * DD; i += 256) { float t = ker[i]; ksq[i] = t * t; }
    vsh[tid] = g_v[b * DD + tid];
    __syncthreads();

    int w = tid >> 5, lane = tid & 31;
    int row = row0 + w;

    uint4 H = reinterpret_cast<const uint4*>(g_x1h)[(size_t)row * 32 + lane];
    uint4 L = reinterpret_cast<const uint4*>(g_x1l)[(size_t)row * 32 + lane];
    __nv_bfloat162 hh[4], ll[4];
    *reinterpret_cast<uint4*>(hh) = H;
    *reinterpret_cast<uint4*>(ll) = L;
    float s[8];
#pragma unroll
    for (int q = 0; q < 4; q++) {
        s[q*2]   = __bfloat162float(hh[q].x) + __bfloat162float(ll[q].x);
        s[q*2+1] = __bfloat162float(hh[q].y) + __bfloat162float(ll[q].y);
    }
    const float4* wp = reinterpret_cast<const float4*>(g_w) + (size_t)row * 64;
    float4 W0 = wp[lane * 2], W1 = wp[lane * 2 + 1];
    float wv[8] = {W0.x, W0.y, W0.z, W0.w, W1.x, W1.y, W1.z, W1.w};

    // rowsum(cos) = x1 . v
    float rs = 0.f;
    const float* vp = &vsh[lane * 8];
#pragma unroll
    for (int i = 0; i < 8; i++) rs += s[i] * vp[i];
#pragma unroll
    for (int o = 16; o; o >>= 1) rs += __shfl_xor_sync(0xffffffffu, rs, o);
    float invd = 1.0f / (rs + EPS);

    float mv[8], sm[8], ssq[8], msq[8];
#pragma unroll
    for (int i = 0; i < 8; i++) {
        mv[i]  = wv[i] * invd;
        sm[i]  = s[i] * mv[i];
        ssq[i] = s[i] * s[i];
        msq[i] = mv[i] * mv[i];
    }

    for (int p = 0; p < PP; p++) {
        const float* kp = &ksq[p * DD + lane * 8];
        float4 K0 = *(const float4*)kp;
        float4 K1 = *(const float4*)(kp + 4);
        float kk[8] = {K0.x, K0.y, K0.z, K0.w, K1.x, K1.y, K1.z, K1.w};
        float n = 0.f, d1 = 0.f, d2 = 0.f;
#pragma unroll
        for (int i = 0; i < 8; i++) {
            n  += kk[i] * sm[i];
            d1 += kk[i] * ssq[i];
            d2 += kk[i] * msq[i];
        }
#pragma unroll
        for (int o = 16; o; o >>= 1) {
            n  += __shfl_xor_sync(0xffffffffu, n,  o);
            d1 += __shfl_xor_sync(0xffffffffu, d1, o);
            d2 += __shfl_xor_sync(0xffffffffu, d2, o);
        }
        if (lane == 0)
            obuf[w][p] = n * rsqrtf(fmaxf(d1, EPS)) * rsqrtf(fmaxf(d2, EPS));
    }
    __syncwarp();
    if (lane < PP) out[(size_t)row * PP + lane] = obuf[w][lane];
}

// ======================= launch =======================
extern "C" void kernel_launch(void* const* d_in, const int* in_sizes, int n_in,
                              void* d_out, int out_size) {
    const float* s1  = (const float*)d_in[0];   // [16,1024,256]
    const float* s2  = (const float*)d_in[1];   // [16,1024,256]
    const float* ker = (const float*)d_in[2];   // [20,256]
    float* out = (float*)d_out;                 // [16,1024,20]

    cudaFuncSetAttribute(k_gram_mma, cudaFuncAttributeMaxDynamicSharedMemorySize, 2*BUFSZ);
    cudaFuncSetAttribute(k_wt_mma,   cudaFuncAttributeMaxDynamicSharedMemorySize, 2*BUFSZ);

    k_prep<<<2048, 256>>>(s1);
    k_trans<<<dim3(16, 32), 256>>>(s2);
    k_vred<<<512, 256>>>();
    k_gram_mma<<<dim3(16, 2, 8), 256, 2*BUFSZ>>>();
    k_mred<<<1024, 256>>>();
    k_wt_mma<<<dim3(16, 8, 4), 256, 2*BUFSZ>>>();
    k_out<<<2048, 256>>>(ker, out);
}